// round 7
// baseline (speedup 1.0000x reference)
#include <cuda_runtime.h>
#include <math.h>
#include <stdint.h>

// Problem constants
#define BV 512
#define TV 64
#define FV 256
#define HV 1024

// Output layout: x_imp [B,T,F] | reconstruction [B,T,F] | h_fin [B,H] | x_loss | kl_loss
#define OFF_REC   (BV*TV*FV)
#define OFF_HFIN  (2*BV*TV*FV)
#define OFF_LOSS  (2*BV*TV*FV + BV*HV)

#define NB2 32   // number of blocks in GEMM2 grid (loss partials per step)

// ---------------- scratch ----------------
__device__ float g_h[BV*HV];
__device__ float g_xh[BV*FV];
__device__ float g_gh[BV*3*HV];
__device__ float g_gi[BV*3*HV];
__device__ float g_gammaH[(size_t)TV*BV*HV];
__device__ float g_beta[(size_t)TV*BV*FV];
__device__ float g_msum[TV];
__device__ float g_lossPart[TV*NB2];

// ---- pre-swizzled tf32 B (weights), uint2 fragment granularity ----
#define SZ2(N,K) ((N)*(K)/2)
#define BOFF_G1 0
#define BOFF_G3 (BOFF_G1 + SZ2(3328,1024))
#define BOFF_G2 (BOFF_G3 + SZ2(3072,512))
#define BOFF_P1 (BOFF_G2 + SZ2(256,256))
#define BOFF_P2 (BOFF_P1 + SZ2(1024,256))
#define BSWZ_TOTAL (BOFF_P2 + SZ2(256,512))
__device__ uint2 g_Bswz[BSWZ_TOTAL];

// ---- pre-swizzled tf32 A (activations), uint32 words, 16B-aligned ----
#define AOFF_G1 0                                   // 512x1024
#define AOFF_G2 (AOFF_G1 + BV*HV)                   // 512x256
#define AOFF_G3 (AOFF_G2 + BV*FV)                   // 64 slices of 512x512
#define AG3_STRIDE (BV*2*FV)
#define AOFF_P1 (AOFF_G3 + TV*AG3_STRIDE)           // 32768x256
#define AOFF_P2 (AOFF_P1 + TV*BV*FV)                // 32768x512
#define ASWZ_TOTAL (AOFF_P2 + TV*BV*2*FV)
__device__ uint4 g_Aswz4[ASWZ_TOTAL/4];
#define ASWZ_W ((uint32_t*)g_Aswz4)

__device__ __forceinline__ uint32_t f2tf(float f) {
    uint32_t r;
    asm("cvt.rna.tf32.f32 %0, %1;" : "=r"(r) : "f"(f));
    return r;
}

// word index of element (m,k) in fragment-native A layout (KTT = K/8)
__device__ __forceinline__ int aidx(int m, int k, int KTT) {
    int r = m & 15, c = k & 7;
    return (((m >> 4)*KTT + (k >> 3))*32 + (r & 7)*4 + (c & 3))*4
           + (r >> 3) + (((k >> 2) & 1) << 1);
}

// ---------------- weight pre-swizzle: B(n,k) -> fragment-native tf32 ----------------
template<class BL>
__global__ void swz_k(int boff, int N, int K, BL bl) {
    int idx = blockIdx.x * 256 + threadIdx.x;
    if (idx >= N*K) return;
    int n = idx / K, k = idx % K;
    int KTT = K >> 3;
    uint32_t* d = (uint32_t*)(g_Bswz + boff);
    int off = (((n>>3)*KTT + (k>>3))*32 + ((n&7)*4 + (k&3)))*2 + ((k>>2)&1);
    d[off] = f2tf(bl(n, k));
}

// ------------- tf32 tensor-core GEMM, BOTH operands pre-swizzled in global -------------
// C[m,n] = sum_k A(m,k)*B(n,k). 256 threads = 8 warps. No smem, no syncthreads in mainloop.
template<int BM,int BN,int WM,int WN,class EP>
__global__ __launch_bounds__(256)
void tgemm3_k(int K, int aoff, int boff, EP ep) {
    constexpr int WARPS_M = BM/WM, WARPS_N = BN/WN;
    static_assert(WARPS_M*WARPS_N == 8, "need 8 warps");
    constexpr int MI = WM/16, NI = WN/8;

    const int KTT = K >> 3;
    const int tid = threadIdx.x, lane = tid & 31, wid = tid >> 5;
    const int wm = (wid % WARPS_M)*WM, wn = (wid / WARPS_M)*WN;
    const int gid = lane >> 2, tig = lane & 3;
    const int bm = blockIdx.y*BM, bn = blockIdx.x*BN;
    const int mtBase = (bm + wm) >> 4;
    const int ntBase = (bn + wn) >> 3;

    const uint4* __restrict__ Ag = (const uint4*)(ASWZ_W + aoff);
    const uint2* __restrict__ Bg = g_Bswz + boff;

    float acc[MI][NI][4];
    #pragma unroll
    for (int mi = 0; mi < MI; mi++)
        #pragma unroll
        for (int ni = 0; ni < NI; ni++)
            #pragma unroll
            for (int c = 0; c < 4; c++) acc[mi][ni][c] = 0.f;

    uint4 avc[MI]; uint2 bfc[NI];
    #pragma unroll
    for (int mi = 0; mi < MI; mi++) avc[mi] = Ag[((mtBase+mi)*KTT)*32 + lane];
    #pragma unroll
    for (int ni = 0; ni < NI; ni++) bfc[ni] = Bg[((ntBase+ni)*KTT)*32 + lane];

    #pragma unroll 4
    for (int kt = 0; kt < KTT; kt++) {
        uint4 avn[MI]; uint2 bfn[NI];
        if (kt + 1 < KTT) {
            #pragma unroll
            for (int mi = 0; mi < MI; mi++) avn[mi] = Ag[((mtBase+mi)*KTT + kt+1)*32 + lane];
            #pragma unroll
            for (int ni = 0; ni < NI; ni++) bfn[ni] = Bg[((ntBase+ni)*KTT + kt+1)*32 + lane];
        }
        #pragma unroll
        for (int mi = 0; mi < MI; mi++)
            #pragma unroll
            for (int ni = 0; ni < NI; ni++)
                asm volatile(
                    "mma.sync.aligned.m16n8k8.row.col.f32.tf32.tf32.f32 "
                    "{%0,%1,%2,%3}, {%4,%5,%6,%7}, {%8,%9}, {%0,%1,%2,%3};"
                    : "+f"(acc[mi][ni][0]), "+f"(acc[mi][ni][1]),
                      "+f"(acc[mi][ni][2]), "+f"(acc[mi][ni][3])
                    : "r"(avc[mi].x), "r"(avc[mi].y), "r"(avc[mi].z), "r"(avc[mi].w),
                      "r"(bfc[ni].x), "r"(bfc[ni].y));
        if (kt + 1 < KTT) {
            #pragma unroll
            for (int mi = 0; mi < MI; mi++) avc[mi] = avn[mi];
            #pragma unroll
            for (int ni = 0; ni < NI; ni++) bfc[ni] = bfn[ni];
        }
    }

    float rsum = 0.f;
    #pragma unroll
    for (int mi = 0; mi < MI; mi++) {
        #pragma unroll
        for (int ni = 0; ni < NI; ni++) {
            int gm0 = bm + wm + mi*16 + gid;
            int gn0 = bn + wn + ni*8 + tig*2;
            rsum += ep(gm0,     gn0,     acc[mi][ni][0]);
            rsum += ep(gm0,     gn0 + 1, acc[mi][ni][1]);
            rsum += ep(gm0 + 8, gn0,     acc[mi][ni][2]);
            rsum += ep(gm0 + 8, gn0 + 1, acc[mi][ni][3]);
        }
    }

    if constexpr (EP::RED) {
        __shared__ float red[256];
        red[tid] = rsum;
        __syncthreads();
        for (int s = 128; s > 0; s >>= 1) {
            if (tid < s) red[tid] += red[tid + s];
            __syncthreads();
        }
        if (tid == 0) {
            int lin = blockIdx.y * gridDim.x + blockIdx.x;
            ep.store_partial(lin, red[0]);
        }
    }
}

// ---------------- B-side scalar loaders (used only by swz_k) ----------------

struct BL_P1 {
    const float* Wdh;
    __device__ float operator()(int n, int k) const { return Wdh[n*FV + k]; }
};
struct BL_P2 {
    const float* Wwc;
    __device__ float operator()(int n, int k) const { return Wwc[n*(2*FV) + k]; }
};
struct BL_G1 {
    const float* Wh; const float* Whh;
    __device__ float operator()(int n, int k) const {
        return (n < FV) ? Wh[n*HV + k] : Whh[(n - FV)*HV + k];
    }
};
struct BL_G2 {
    const float* Wfr;
    __device__ float operator()(int n, int k) const {
        return (n == k) ? 0.f : Wfr[n*FV + k];
    }
};
struct BL_G3 {
    const float* Wih;
    __device__ float operator()(int n, int k) const { return Wih[n*(2*FV) + k]; }
};

// ---------------- A-side pre-swizzle kernels ----------------

// P1 A = deltas, m = t*B+b, K=256
__global__ void swzA_P1_k(const float* __restrict__ deltas) {
    int idx = blockIdx.x * 256 + threadIdx.x;   // 32768*256
    int m = idx >> 8, k = idx & 255;
    int t = m >> 9, b = m & 511;
    ASWZ_W[AOFF_P1 + aidx(m, k, 32)] = f2tf(deltas[(b*TV + t)*FV + k]);
}

// P2 A = [gamma_x | mask], K=512
__global__ void swzA_P2_k(const float* __restrict__ deltas, const float* __restrict__ mask,
                          const float* __restrict__ Wdx, const float* __restrict__ bdx) {
    int idx = blockIdx.x * 256 + threadIdx.x;   // 32768*512
    int m = idx >> 9, k = idx & 511;
    int t = m >> 9, b = m & 511;
    float v;
    if (k < FV) {
        float d = deltas[(b*TV + t)*FV + k];
        v = expf(-fmaxf(d * Wdx[k*FV + k] + bdx[k], 0.f));
    } else {
        v = mask[(b*TV + t)*FV + (k - FV)];
    }
    ASWZ_W[AOFF_P2 + aidx(m, k, 64)] = f2tf(v);
}

// G3 A mask half (k in [256,512)), all t slices
__global__ void swzA_G3m_k(const float* __restrict__ mask) {
    int idx = blockIdx.x * 256 + threadIdx.x;   // 64*512*256
    int t = idx >> 17, b = (idx >> 8) & 511, f = idx & 255;
    ASWZ_W[AOFF_G3 + t*AG3_STRIDE + aidx(b, FV + f, 64)] =
        f2tf(mask[(b*TV + t)*FV + f]);
}

// h init: plain h0 + swizzled h0*gammaH[0] (run after P1 GEMM)
__global__ void hAinit_k(const float* __restrict__ h0) {
    int idx = blockIdx.x * 256 + threadIdx.x;   // B*H
    int b = idx >> 10, j = idx & 1023;
    float h = h0[idx];
    g_h[idx] = h;
    ASWZ_W[AOFF_G1 + aidx(b, j, 128)] = f2tf(h * g_gammaH[idx]);
}

// ---------------- epilogues ----------------

struct EP_P1 {
    const float* bdh;
    static constexpr bool RED = false;
    __device__ float operator()(int m, int n, float v) const {
        g_gammaH[(size_t)m*HV + n] = expf(-fmaxf(v + bdh[n], 0.f));
        return 0.f;
    }
    __device__ void store_partial(int, float) const {}
};
struct EP_P2 {
    const float* bwc;
    static constexpr bool RED = false;
    __device__ float operator()(int m, int n, float v) const {
        g_beta[(size_t)m*FV + n] = v + bwc[n];
        return 0.f;
    }
    __device__ void store_partial(int, float) const {}
};
// G1 epilogue: n<F -> x_h (plain) + swizzled x_r for G2 A ; else gh
struct EP_G1 {
    const float* bh; const float* bhh; const float* x; const float* mask; int t;
    static constexpr bool RED = false;
    __device__ float operator()(int m, int n, float v) const {
        if (n < FV) {
            float xh = v + bh[n];
            g_xh[m*FV + n] = xh;
            int idx = (m*TV + t)*FV + n;
            float mt = mask[idx];
            float xr = mt * x[idx] + (1.f - mt) * xh;
            ASWZ_W[AOFF_G2 + aidx(m, n, 32)] = f2tf(xr);
        } else {
            g_gh[m*3*HV + (n - FV)] = v + bhh[n - FV];
        }
        return 0.f;
    }
    __device__ void store_partial(int, float) const {}
};
// G2 epilogue: combine, write rec/ximp outputs + swizzled ximp into G3 A slice, loss partial
struct EP_G2 {
    const float* bfr; const float* x; const float* mask;
    float* rec; float* ximp; int t;
    static constexpr bool RED = true;
    __device__ float operator()(int m, int n, float v) const {
        float xu = v + bfr[n];
        float xh = g_xh[m*FV + n];
        float be = g_beta[(size_t)t*BV*FV + m*FV + n];
        float xc = be * xu + (1.f - be) * xh;
        int idx = (m*TV + t)*FV + n;
        float mt = mask[idx], xt = x[idx];
        rec[idx]  = xc;
        float xi = mt * xt + (1.f - mt) * xc;
        ximp[idx] = xi;
        ASWZ_W[AOFF_G3 + t*AG3_STRIDE + aidx(m, n, 64)] = f2tf(xi);
        return fabsf(xc - xt) * mt;
    }
    __device__ void store_partial(int lin, float v) const {
        g_lossPart[t*NB2 + lin] = v;
    }
};
struct EP_G3 {
    const float* bih;
    static constexpr bool RED = false;
    __device__ float operator()(int m, int n, float v) const {
        g_gi[m*3*HV + n] = v + bih[n];
        return 0.f;
    }
    __device__ void store_partial(int, float) const {}
};

// ---------------- elementwise kernels ----------------

__global__ void msum_k(const float* __restrict__ mask) {
    int t = blockIdx.x;
    float s = 0.f;
    for (int i = threadIdx.x; i < BV*FV; i += 256) {
        int b = i >> 8, f = i & 255;
        s += mask[(b*TV + t)*FV + f];
    }
    __shared__ float red[256];
    red[threadIdx.x] = s;
    __syncthreads();
    for (int st = 128; st > 0; st >>= 1) {
        if (threadIdx.x < st) red[threadIdx.x] += red[threadIdx.x + st];
        __syncthreads();
    }
    if (threadIdx.x == 0) g_msum[t] = red[0];
}

// GRU update; also produces next step's swizzled A (h_new * gammaH[t+1])
__global__ void gru_k(int t, float* __restrict__ hfin) {
    int idx = blockIdx.x * blockDim.x + threadIdx.x;  // B*H
    int b = idx >> 10, j = idx & 1023;
    float hd = g_h[idx] * g_gammaH[(size_t)t*BV*HV + idx];
    int base = b*3*HV + j;
    float r = 1.f / (1.f + expf(-(g_gi[base]        + g_gh[base])));
    float z = 1.f / (1.f + expf(-(g_gi[base + HV]   + g_gh[base + HV])));
    float n = tanhf(g_gi[base + 2*HV] + r * g_gh[base + 2*HV]);
    float hn = (1.f - z) * n + z * hd;
    g_h[idx] = hn;
    if (t + 1 < TV)
        ASWZ_W[AOFF_G1 + aidx(b, j, 128)] =
            f2tf(hn * g_gammaH[(size_t)(t+1)*BV*HV + idx]);
    if (hfin) hfin[idx] = hn;
}

__global__ void final_k(float* __restrict__ out) {
    __shared__ float s[TV];
    int t = threadIdx.x;  // 64 threads
    float acc = 0.f;
    for (int i = 0; i < NB2; i++) acc += g_lossPart[t*NB2 + i];
    s[t] = acc / (g_msum[t] + 1e-12f);
    __syncthreads();
    if (t == 0) {
        float L = 0.f;
        for (int i = 0; i < TV; i++) L += s[i];
        out[OFF_LOSS]     = L;
        out[OFF_LOSS + 1] = 0.f;  // kl_loss
    }
}

// ---------------- launch ----------------

extern "C" void kernel_launch(void* const* d_in, const int* in_sizes, int n_in,
                              void* d_out, int out_size) {
    const float* x      = (const float*)d_in[0];
    const float* mask   = (const float*)d_in[1];
    const float* deltas = (const float*)d_in[2];
    const float* h0     = (const float*)d_in[3];
    const float* Wdh    = (const float*)d_in[4];
    const float* bdh    = (const float*)d_in[5];
    const float* Wdx    = (const float*)d_in[6];
    const float* bdx    = (const float*)d_in[7];
    const float* Wh     = (const float*)d_in[8];
    const float* bh     = (const float*)d_in[9];
    const float* Wfr    = (const float*)d_in[10];
    const float* bfr    = (const float*)d_in[11];
    const float* Wwc    = (const float*)d_in[12];
    const float* bwc    = (const float*)d_in[13];
    const float* Wih    = (const float*)d_in[14];
    const float* bih    = (const float*)d_in[15];
    const float* Whh    = (const float*)d_in[16];
    const float* bhh    = (const float*)d_in[17];

    float* out      = (float*)d_out;
    float* ximp_out = out;
    float* rec_out  = out + OFF_REC;
    float* hfin     = out + OFF_HFIN;

    msum_k<<<TV, 256>>>(mask);

    // Pre-swizzle weights (B operands)
    swz_k<<<(3328*1024)/256, 256>>>(BOFF_G1, 3328, 1024, BL_G1{Wh, Whh});
    swz_k<<<(3072*512 )/256, 256>>>(BOFF_G3, 3072, 512,  BL_G3{Wih});
    swz_k<<<(256*256  )/256, 256>>>(BOFF_G2, 256,  256,  BL_G2{Wfr});
    swz_k<<<(1024*256 )/256, 256>>>(BOFF_P1, 1024, 256,  BL_P1{Wdh});
    swz_k<<<(256*512  )/256, 256>>>(BOFF_P2, 256,  512,  BL_P2{Wwc});

    // Pre-swizzle A operands for P1/P2 and G3 mask half
    swzA_P1_k<<<(32768*256)/256, 256>>>(deltas);
    swzA_P2_k<<<(32768*512)/256, 256>>>(deltas, mask, Wdx, bdx);
    swzA_G3m_k<<<(TV*BV*FV)/256, 256>>>(mask);

    // P1: gammaH, M=32768, N=1024, K=256
    tgemm3_k<64,128,32,32><<<dim3(1024/128, 32768/64), 256>>>(
        FV, AOFF_P1, BOFF_P1, EP_P1{bdh});

    // h init (needs gammaH[0])
    hAinit_k<<<(BV*HV)/256, 256>>>(h0);

    // P2: beta, M=32768, N=256, K=512
    tgemm3_k<64,128,32,32><<<dim3(256/128, 32768/64), 256>>>(
        2*FV, AOFF_P2, BOFF_P2, EP_P2{bwc});

    for (int t = 0; t < TV; t++) {
        // G1: [x_h | gh], M=512, N=3328, K=1024 -> 208 blocks
        tgemm3_k<64,128,32,32><<<dim3(3328/128, 512/64), 256>>>(
            HV, AOFF_G1, BOFF_G1, EP_G1{bh, bhh, x, mask, t});

        // G2: xu + combine/imputation/loss, M=512, N=256, K=256 -> 32 blocks
        tgemm3_k<64,64,32,16><<<dim3(256/64, 512/64), 256>>>(
            FV, AOFF_G2, BOFF_G2, EP_G2{bfr, x, mask, rec_out, ximp_out, t});

        // G3: gi, M=512, N=3072, K=512 -> 192 blocks
        tgemm3_k<64,128,32,32><<<dim3(3072/128, 512/64), 256>>>(
            2*FV, AOFF_G3 + t*AG3_STRIDE, BOFF_G3, EP_G3{bih});

        // GRU elementwise update (+ next step's swizzled A)
        gru_k<<<(BV*HV)/256, 256>>>(t, (t == TV-1) ? hfin : nullptr);
    }

    final_k<<<1, TV>>>(out);
}

// round 8
// speedup vs baseline: 1.5596x; 1.5596x over previous
#include <cuda_runtime.h>
#include <math.h>
#include <stdint.h>

// Problem constants
#define BV 512
#define TV 64
#define FV 256
#define HV 1024

// Output layout: x_imp [B,T,F] | reconstruction [B,T,F] | h_fin [B,H] | x_loss | kl_loss
#define OFF_REC   (BV*TV*FV)
#define OFF_HFIN  (2*BV*TV*FV)
#define OFF_LOSS  (2*BV*TV*FV + BV*HV)

#define NB2 32   // number of blocks in GEMM2 grid (loss partials per step)

// ---------------- scratch ----------------
__device__ float g_h[BV*HV];
__device__ float g_xh[BV*FV];
__device__ float g_gh[BV*3*HV];
__device__ float g_gi[BV*3*HV];
__device__ float g_gammaH[(size_t)TV*BV*HV];
__device__ float g_beta[(size_t)TV*BV*FV];
__device__ float g_msum[TV];
__device__ float g_lossPart[TV*NB2];

// ---- pre-swizzled tf32 B (weights), uint2 fragment granularity ----
#define SZ2(N,K) ((N)*(K)/2)
#define BOFF_G1 0
#define BOFF_G3 (BOFF_G1 + SZ2(3328,1024))
#define BOFF_G2 (BOFF_G3 + SZ2(3072,512))
#define BOFF_P1 (BOFF_G2 + SZ2(256,256))
#define BOFF_P2 (BOFF_P1 + SZ2(1024,256))
#define BSWZ_TOTAL (BOFF_P2 + SZ2(256,512))
__device__ uint2 g_Bswz[BSWZ_TOTAL];

// ---- pre-swizzled tf32 A (activations), uint32 words, 16B-aligned ----
#define AOFF_G1 0                                   // 512x1024
#define AOFF_G2 (AOFF_G1 + BV*HV)                   // 512x256
#define AOFF_G3 (AOFF_G2 + BV*FV)                   // 64 slices of 512x512
#define AG3_STRIDE (BV*2*FV)
#define AOFF_P1 (AOFF_G3 + TV*AG3_STRIDE)           // 32768x256
#define AOFF_P2 (AOFF_P1 + TV*BV*FV)                // 32768x512
#define ASWZ_TOTAL (AOFF_P2 + TV*BV*2*FV)
__device__ uint4 g_Aswz4[ASWZ_TOTAL/4];
#define ASWZ_W ((uint32_t*)g_Aswz4)

__device__ __forceinline__ uint32_t f2tf(float f) {
    uint32_t r;
    asm("cvt.rna.tf32.f32 %0, %1;" : "=r"(r) : "f"(f));
    return r;
}

// word index of element (m,k) in fragment-native A layout (KTT = K/8)
__device__ __forceinline__ int aidx(int m, int k, int KTT) {
    int r = m & 15, c = k & 7;
    return (((m >> 4)*KTT + (k >> 3))*32 + (r & 7)*4 + (c & 3))*4
           + (r >> 3) + (((k >> 2) & 1) << 1);
}

// ---------------- weight pre-swizzle: B(n,k) -> fragment-native tf32 ----------------
template<class BL>
__global__ void swz_k(int boff, int N, int K, BL bl) {
    int idx = blockIdx.x * 256 + threadIdx.x;
    if (idx >= N*K) return;
    int n = idx / K, k = idx % K;
    int KTT = K >> 3;
    uint32_t* d = (uint32_t*)(g_Bswz + boff);
    int off = (((n>>3)*KTT + (k>>3))*32 + ((n&7)*4 + (k&3)))*2 + ((k>>2)&1);
    d[off] = f2tf(bl(n, k));
}

// ------------- tf32 tensor-core GEMM: pre-swizzled A staged via smem, B direct LDG -------------
// C[m,n] = sum_k A(m,k)*B(n,k). 256 threads = 8 warps. BK = 32 (KT = 4 k8-tiles).
// A feeder = pure coalesced uint4 copy global->smem (double buffered); no cvt, no index math.
template<int BM,int BN,int WM,int WN,class EP>
__global__ __launch_bounds__(256, 2)
void tgemm4_k(int K, int aoff, int boff, EP ep) {
    constexpr int WARPS_M = BM/WM, WARPS_N = BN/WN;
    static_assert(WARPS_M*WARPS_N == 8, "need 8 warps");
    constexpr int MI = WM/16, NI = WN/8;
    constexpr int KT = 4;                         // k8-tiles per BK=32 tile
    constexpr int TILE4 = (BM/16)*KT*32;          // uint4 per A tile
    constexpr int CP = TILE4/256;                 // uint4 per thread per copy

    __shared__ uint4 As[2][TILE4];

    const int KTT = K >> 3;
    const int tid = threadIdx.x, lane = tid & 31, wid = tid >> 5;
    const int wm = (wid % WARPS_M)*WM, wn = (wid / WARPS_M)*WN;
    const int gid = lane >> 2, tig = lane & 3;
    const int bm = blockIdx.y*BM, bn = blockIdx.x*BN;
    const int mtBase = bm >> 4;
    const int ntBase = (bn + wn) >> 3;
    const int wmt = wm >> 4;

    const uint4* __restrict__ Ag = (const uint4*)(ASWZ_W + aoff);
    const uint2* __restrict__ Bg = g_Bswz + boff;

    float acc[MI][NI][4];
    #pragma unroll
    for (int mi = 0; mi < MI; mi++)
        #pragma unroll
        for (int ni = 0; ni < NI; ni++)
            #pragma unroll
            for (int c = 0; c < 4; c++) acc[mi][ni][c] = 0.f;

    // copy-element decomposition (compile-time per i)
    uint4 ar[CP];
    auto ldA = [&](int kt0) {
        #pragma unroll
        for (int i = 0; i < CP; i++) {
            int e = tid + i*256;
            int mtl = e / (KT*32), rem = e % (KT*32);
            ar[i] = Ag[((mtBase + mtl)*KTT + kt0 + rem/32)*32 + (rem & 31)];
        }
    };
    auto stA = [&](int buf) {
        #pragma unroll
        for (int i = 0; i < CP; i++) As[buf][tid + i*256] = ar[i];
    };

    ldA(0); stA(0);
    __syncthreads();

    int cur = 0;
    for (int kt0 = 0; kt0 < KTT; kt0 += KT) {
        const bool more = (kt0 + KT) < KTT;
        // B fragments for this tile: direct LDG.64 from pre-swizzled global
        uint2 bf[NI][KT];
        #pragma unroll
        for (int ni = 0; ni < NI; ni++)
            #pragma unroll
            for (int kk = 0; kk < KT; kk++)
                bf[ni][kk] = Bg[((ntBase + ni)*KTT + kt0 + kk)*32 + lane];
        if (more) ldA(kt0 + KT);

        #pragma unroll
        for (int kk = 0; kk < KT; kk++) {
            uint4 av[MI];
            #pragma unroll
            for (int mi = 0; mi < MI; mi++)
                av[mi] = As[cur][((wmt + mi)*KT + kk)*32 + lane];
            #pragma unroll
            for (int mi = 0; mi < MI; mi++)
                #pragma unroll
                for (int ni = 0; ni < NI; ni++)
                    asm volatile(
                        "mma.sync.aligned.m16n8k8.row.col.f32.tf32.tf32.f32 "
                        "{%0,%1,%2,%3}, {%4,%5,%6,%7}, {%8,%9}, {%0,%1,%2,%3};"
                        : "+f"(acc[mi][ni][0]), "+f"(acc[mi][ni][1]),
                          "+f"(acc[mi][ni][2]), "+f"(acc[mi][ni][3])
                        : "r"(av[mi].x), "r"(av[mi].y), "r"(av[mi].z), "r"(av[mi].w),
                          "r"(bf[ni][kk].x), "r"(bf[ni][kk].y));
        }
        if (more) stA(cur ^ 1);
        __syncthreads();
        cur ^= 1;
    }

    float rsum = 0.f;
    #pragma unroll
    for (int mi = 0; mi < MI; mi++) {
        #pragma unroll
        for (int ni = 0; ni < NI; ni++) {
            int gm0 = bm + wm + mi*16 + gid;
            int gn0 = bn + wn + ni*8 + tig*2;
            rsum += ep(gm0,     gn0,     acc[mi][ni][0]);
            rsum += ep(gm0,     gn0 + 1, acc[mi][ni][1]);
            rsum += ep(gm0 + 8, gn0,     acc[mi][ni][2]);
            rsum += ep(gm0 + 8, gn0 + 1, acc[mi][ni][3]);
        }
    }

    if constexpr (EP::RED) {
        __shared__ float red[256];
        red[tid] = rsum;
        __syncthreads();
        for (int s = 128; s > 0; s >>= 1) {
            if (tid < s) red[tid] += red[tid + s];
            __syncthreads();
        }
        if (tid == 0) {
            int lin = blockIdx.y * gridDim.x + blockIdx.x;
            ep.store_partial(lin, red[0]);
        }
    }
}

// ---------------- B-side scalar loaders (used only by swz_k) ----------------

struct BL_P1 {
    const float* Wdh;
    __device__ float operator()(int n, int k) const { return Wdh[n*FV + k]; }
};
struct BL_P2 {
    const float* Wwc;
    __device__ float operator()(int n, int k) const { return Wwc[n*(2*FV) + k]; }
};
struct BL_G1 {
    const float* Wh; const float* Whh;
    __device__ float operator()(int n, int k) const {
        return (n < FV) ? Wh[n*HV + k] : Whh[(n - FV)*HV + k];
    }
};
struct BL_G2 {
    const float* Wfr;
    __device__ float operator()(int n, int k) const {
        return (n == k) ? 0.f : Wfr[n*FV + k];
    }
};
struct BL_G3 {
    const float* Wih;
    __device__ float operator()(int n, int k) const { return Wih[n*(2*FV) + k]; }
};

// ---------------- A-side pre-swizzle kernels ----------------

// P1 A = deltas, m = t*B+b, K=256
__global__ void swzA_P1_k(const float* __restrict__ deltas) {
    int idx = blockIdx.x * 256 + threadIdx.x;   // 32768*256
    int m = idx >> 8, k = idx & 255;
    int t = m >> 9, b = m & 511;
    ASWZ_W[AOFF_P1 + aidx(m, k, 32)] = f2tf(deltas[(b*TV + t)*FV + k]);
}

// P2 A = [gamma_x | mask], K=512
__global__ void swzA_P2_k(const float* __restrict__ deltas, const float* __restrict__ mask,
                          const float* __restrict__ Wdx, const float* __restrict__ bdx) {
    int idx = blockIdx.x * 256 + threadIdx.x;   // 32768*512
    int m = idx >> 9, k = idx & 511;
    int t = m >> 9, b = m & 511;
    float v;
    if (k < FV) {
        float d = deltas[(b*TV + t)*FV + k];
        v = expf(-fmaxf(d * Wdx[k*FV + k] + bdx[k], 0.f));
    } else {
        v = mask[(b*TV + t)*FV + (k - FV)];
    }
    ASWZ_W[AOFF_P2 + aidx(m, k, 64)] = f2tf(v);
}

// G3 A mask half (k in [256,512)), all t slices
__global__ void swzA_G3m_k(const float* __restrict__ mask) {
    int idx = blockIdx.x * 256 + threadIdx.x;   // 64*512*256
    int t = idx >> 17, b = (idx >> 8) & 511, f = idx & 255;
    ASWZ_W[AOFF_G3 + t*AG3_STRIDE + aidx(b, FV + f, 64)] =
        f2tf(mask[(b*TV + t)*FV + f]);
}

// h init: plain h0 + swizzled h0*gammaH[0] (run after P1 GEMM)
__global__ void hAinit_k(const float* __restrict__ h0) {
    int idx = blockIdx.x * 256 + threadIdx.x;   // B*H
    int b = idx >> 10, j = idx & 1023;
    float h = h0[idx];
    g_h[idx] = h;
    ASWZ_W[AOFF_G1 + aidx(b, j, 128)] = f2tf(h * g_gammaH[idx]);
}

// ---------------- epilogues ----------------

struct EP_P1 {
    const float* bdh;
    static constexpr bool RED = false;
    __device__ float operator()(int m, int n, float v) const {
        g_gammaH[(size_t)m*HV + n] = expf(-fmaxf(v + bdh[n], 0.f));
        return 0.f;
    }
    __device__ void store_partial(int, float) const {}
};
struct EP_P2 {
    const float* bwc;
    static constexpr bool RED = false;
    __device__ float operator()(int m, int n, float v) const {
        g_beta[(size_t)m*FV + n] = v + bwc[n];
        return 0.f;
    }
    __device__ void store_partial(int, float) const {}
};
// G1 epilogue: n<F -> x_h (plain) + swizzled x_r for G2 A ; else gh
struct EP_G1 {
    const float* bh; const float* bhh; const float* x; const float* mask; int t;
    static constexpr bool RED = false;
    __device__ float operator()(int m, int n, float v) const {
        if (n < FV) {
            float xh = v + bh[n];
            g_xh[m*FV + n] = xh;
            int idx = (m*TV + t)*FV + n;
            float mt = mask[idx];
            float xr = mt * x[idx] + (1.f - mt) * xh;
            ASWZ_W[AOFF_G2 + aidx(m, n, 32)] = f2tf(xr);
        } else {
            g_gh[m*3*HV + (n - FV)] = v + bhh[n - FV];
        }
        return 0.f;
    }
    __device__ void store_partial(int, float) const {}
};
// G2 epilogue: combine, write rec/ximp outputs + swizzled ximp into G3 A slice, loss partial
struct EP_G2 {
    const float* bfr; const float* x; const float* mask;
    float* rec; float* ximp; int t;
    static constexpr bool RED = true;
    __device__ float operator()(int m, int n, float v) const {
        float xu = v + bfr[n];
        float xh = g_xh[m*FV + n];
        float be = g_beta[(size_t)t*BV*FV + m*FV + n];
        float xc = be * xu + (1.f - be) * xh;
        int idx = (m*TV + t)*FV + n;
        float mt = mask[idx], xt = x[idx];
        rec[idx]  = xc;
        float xi = mt * xt + (1.f - mt) * xc;
        ximp[idx] = xi;
        ASWZ_W[AOFF_G3 + t*AG3_STRIDE + aidx(m, n, 64)] = f2tf(xi);
        return fabsf(xc - xt) * mt;
    }
    __device__ void store_partial(int lin, float v) const {
        g_lossPart[t*NB2 + lin] = v;
    }
};
struct EP_G3 {
    const float* bih;
    static constexpr bool RED = false;
    __device__ float operator()(int m, int n, float v) const {
        g_gi[m*3*HV + n] = v + bih[n];
        return 0.f;
    }
    __device__ void store_partial(int, float) const {}
};

// ---------------- elementwise kernels ----------------

__global__ void msum_k(const float* __restrict__ mask) {
    int t = blockIdx.x;
    float s = 0.f;
    for (int i = threadIdx.x; i < BV*FV; i += 256) {
        int b = i >> 8, f = i & 255;
        s += mask[(b*TV + t)*FV + f];
    }
    __shared__ float red[256];
    red[threadIdx.x] = s;
    __syncthreads();
    for (int st = 128; st > 0; st >>= 1) {
        if (threadIdx.x < st) red[threadIdx.x] += red[threadIdx.x + st];
        __syncthreads();
    }
    if (threadIdx.x == 0) g_msum[t] = red[0];
}

// GRU update; also produces next step's swizzled A (h_new * gammaH[t+1])
__global__ void gru_k(int t, float* __restrict__ hfin) {
    int idx = blockIdx.x * blockDim.x + threadIdx.x;  // B*H
    int b = idx >> 10, j = idx & 1023;
    float hd = g_h[idx] * g_gammaH[(size_t)t*BV*HV + idx];
    int base = b*3*HV + j;
    float r = 1.f / (1.f + expf(-(g_gi[base]        + g_gh[base])));
    float z = 1.f / (1.f + expf(-(g_gi[base + HV]   + g_gh[base + HV])));
    float n = tanhf(g_gi[base + 2*HV] + r * g_gh[base + 2*HV]);
    float hn = (1.f - z) * n + z * hd;
    g_h[idx] = hn;
    if (t + 1 < TV)
        ASWZ_W[AOFF_G1 + aidx(b, j, 128)] =
            f2tf(hn * g_gammaH[(size_t)(t+1)*BV*HV + idx]);
    if (hfin) hfin[idx] = hn;
}

__global__ void final_k(float* __restrict__ out) {
    __shared__ float s[TV];
    int t = threadIdx.x;  // 64 threads
    float acc = 0.f;
    for (int i = 0; i < NB2; i++) acc += g_lossPart[t*NB2 + i];
    s[t] = acc / (g_msum[t] + 1e-12f);
    __syncthreads();
    if (t == 0) {
        float L = 0.f;
        for (int i = 0; i < TV; i++) L += s[i];
        out[OFF_LOSS]     = L;
        out[OFF_LOSS + 1] = 0.f;  // kl_loss
    }
}

// ---------------- launch ----------------

extern "C" void kernel_launch(void* const* d_in, const int* in_sizes, int n_in,
                              void* d_out, int out_size) {
    const float* x      = (const float*)d_in[0];
    const float* mask   = (const float*)d_in[1];
    const float* deltas = (const float*)d_in[2];
    const float* h0     = (const float*)d_in[3];
    const float* Wdh    = (const float*)d_in[4];
    const float* bdh    = (const float*)d_in[5];
    const float* Wdx    = (const float*)d_in[6];
    const float* bdx    = (const float*)d_in[7];
    const float* Wh     = (const float*)d_in[8];
    const float* bh     = (const float*)d_in[9];
    const float* Wfr    = (const float*)d_in[10];
    const float* bfr    = (const float*)d_in[11];
    const float* Wwc    = (const float*)d_in[12];
    const float* bwc    = (const float*)d_in[13];
    const float* Wih    = (const float*)d_in[14];
    const float* bih    = (const float*)d_in[15];
    const float* Whh    = (const float*)d_in[16];
    const float* bhh    = (const float*)d_in[17];

    float* out      = (float*)d_out;
    float* ximp_out = out;
    float* rec_out  = out + OFF_REC;
    float* hfin     = out + OFF_HFIN;

    msum_k<<<TV, 256>>>(mask);

    // Pre-swizzle weights (B operands)
    swz_k<<<(3328*1024)/256, 256>>>(BOFF_G1, 3328, 1024, BL_G1{Wh, Whh});
    swz_k<<<(3072*512 )/256, 256>>>(BOFF_G3, 3072, 512,  BL_G3{Wih});
    swz_k<<<(256*256  )/256, 256>>>(BOFF_G2, 256,  256,  BL_G2{Wfr});
    swz_k<<<(1024*256 )/256, 256>>>(BOFF_P1, 1024, 256,  BL_P1{Wdh});
    swz_k<<<(256*512  )/256, 256>>>(BOFF_P2, 256,  512,  BL_P2{Wwc});

    // Pre-swizzle A operands for P1/P2 and G3 mask half
    swzA_P1_k<<<(32768*256)/256, 256>>>(deltas);
    swzA_P2_k<<<(32768*512)/256, 256>>>(deltas, mask, Wdx, bdx);
    swzA_G3m_k<<<(TV*BV*FV)/256, 256>>>(mask);

    // P1: gammaH, M=32768, N=1024, K=256
    tgemm4_k<64,128,32,32><<<dim3(1024/128, 32768/64), 256>>>(
        FV, AOFF_P1, BOFF_P1, EP_P1{bdh});

    // h init (needs gammaH[0])
    hAinit_k<<<(BV*HV)/256, 256>>>(h0);

    // P2: beta, M=32768, N=256, K=512
    tgemm4_k<64,128,32,32><<<dim3(256/128, 32768/64), 256>>>(
        2*FV, AOFF_P2, BOFF_P2, EP_P2{bwc});

    for (int t = 0; t < TV; t++) {
        // G1: [x_h | gh], M=512, N=3328, K=1024 -> 208 blocks
        tgemm4_k<64,128,32,32><<<dim3(3328/128, 512/64), 256>>>(
            HV, AOFF_G1, BOFF_G1, EP_G1{bh, bhh, x, mask, t});

        // G2: xu + combine/imputation/loss, M=512, N=256, K=256 -> 32 blocks
        tgemm4_k<64,64,32,16><<<dim3(256/64, 512/64), 256>>>(
            FV, AOFF_G2, BOFF_G2, EP_G2{bfr, x, mask, rec_out, ximp_out, t});

        // G3: gi, M=512, N=3072, K=512 -> 192 blocks
        tgemm4_k<64,128,32,32><<<dim3(3072/128, 512/64), 256>>>(
            2*FV, AOFF_G3 + t*AG3_STRIDE, BOFF_G3, EP_G3{bih});

        // GRU elementwise update (+ next step's swizzled A)
        gru_k<<<(BV*HV)/256, 256>>>(t, (t == TV-1) ? hfin : nullptr);
    }

    final_k<<<1, TV>>>(out);
}